// round 4
// baseline (speedup 1.0000x reference)
#include <cuda_runtime.h>
#include <cstdint>

#define T_STEPS 512
#define BATCH   2048
#define IN_DIM  12
#define E_DIM   15
#define H_DIM   20
#define ROWS_PB 7
#define NTHREADS (ROWS_PB * H_DIM * 2)              // 280 (2 gate-threads per cell)
#define NGRID   ((BATCH + ROWS_PB - 1) / ROWS_PB)   // 293 -> 2 blocks/SM

// ---- packed f32x2 helpers (Blackwell sm_103a) ----
__device__ __forceinline__ unsigned long long pack2(float x, float y) {
    unsigned long long u;
    asm("mov.b64 %0, {%1, %2};" : "=l"(u) : "f"(x), "f"(y));
    return u;
}
__device__ __forceinline__ void fma2(unsigned long long& d,
                                     unsigned long long a,
                                     unsigned long long b) {
    asm("fma.rn.f32x2 %0, %1, %2, %0;" : "+l"(d) : "l"(a), "l"(b));
}
__device__ __forceinline__ float hsum2(unsigned long long u) {
    float x, y;
    asm("mov.b64 {%0, %1}, %2;" : "=f"(x), "=f"(y) : "l"(u));
    return x + y;
}
__device__ __forceinline__ float tanh_a(float x) {
    float y;
    asm("tanh.approx.f32 %0, %1;" : "=f"(y) : "f"(x));
    return y;
}
__device__ __forceinline__ float sig_a(float x) {        // sigmoid via 1 MUFU
    return fmaf(0.5f, tanh_a(0.5f * x), 0.5f);
}
// 16B shared load (4 floats) straight into two aligned u64 pairs
__device__ __forceinline__ void lds2(unsigned long long& a, unsigned long long& b,
                                     const float* p) {
    uint32_t addr = (uint32_t)__cvta_generic_to_shared(p);
    asm volatile("ld.shared.v2.b64 {%0, %1}, [%2];" : "=l"(a), "=l"(b) : "r"(addr));
}

__global__ void __launch_bounds__(NTHREADS, 2)
lstm_tracker_kernel(const float* __restrict__ X,
                    const float* __restrict__ Wemb, const float* __restrict__ bemb,
                    const float* __restrict__ Wih,  const float* __restrict__ bih,
                    const float* __restrict__ Whh,  const float* __restrict__ bhh,
                    const float* __restrict__ Wout, const float* __restrict__ bout,
                    float* __restrict__ out)
{
    __shared__ __align__(16) float s_wemb[E_DIM * IN_DIM];
    __shared__ __align__(16) float s_wih[4 * H_DIM * E_DIM];
    __shared__ __align__(16) float s_wout[3 * H_DIM];
    __shared__ float s_bout[3];
    __shared__ float s_bemb[E_DIM];
    __shared__ __align__(16) float x_s[3][ROWS_PB][IN_DIM];  // 3-deep ring
    __shared__ __align__(16) float h_s[2][ROWS_PB][H_DIM];   // ping-pong

    const int tid  = threadIdx.x;
    const int half = tid & 1;                  // 0: gates i,g   1: gates f,o
    const int k    = (tid >> 1) % H_DIM;       // hidden unit
    const int row  = tid / (H_DIM * 2);        // local batch row
    const int grow = blockIdx.x * ROWS_PB + row;
    const bool valid = grow < BATCH;

    // ---- cooperative weight staging ----
    for (int i = tid; i < E_DIM * IN_DIM; i += NTHREADS)     s_wemb[i] = Wemb[i];
    for (int i = tid; i < 4 * H_DIM * E_DIM; i += NTHREADS)  s_wih[i]  = Wih[i];
    if (tid < 3 * H_DIM) s_wout[tid] = Wout[tid];
    if (tid < 3)         s_bout[tid] = bout[tid];
    if (tid < E_DIM)     s_bemb[tid] = bemb[tid];
    for (int i = tid; i < 2 * ROWS_PB * H_DIM; i += NTHREADS)
        (&h_s[0][0][0])[i] = 0.0f;
    for (int i = tid; i < 3 * ROWS_PB * IN_DIM; i += NTHREADS)
        (&x_s[0][0][0])[i] = 0.0f;
    __syncthreads();

    // ---- per-thread register weights for gates g0=half, g1=half+2 ----
    // Fused:  Wc[r][j] = sum_e Wih[r][e]*Wemb[e][j]
    //         bc[r]    = bih[r] + bhh[r] + sum_e Wih[r][e]*bemb[e]
    float bc[2];
    unsigned long long wc[2][IN_DIM / 2];   // 12 u64
    unsigned long long wh[2][H_DIM / 2];    // 20 u64
#pragma unroll
    for (int gi = 0; gi < 2; ++gi) {
        const int r = (half + 2 * gi) * H_DIM + k;
        float b = bih[r] + bhh[r];
#pragma unroll
        for (int e = 0; e < E_DIM; ++e) b += s_wih[r * E_DIM + e] * s_bemb[e];
        bc[gi] = b;
#pragma unroll
        for (int jj = 0; jj < IN_DIM / 2; ++jj) {
            float c0 = 0.0f, c1 = 0.0f;
#pragma unroll
            for (int e = 0; e < E_DIM; ++e) {
                const float wie = s_wih[r * E_DIM + e];
                c0 += wie * s_wemb[e * IN_DIM + 2 * jj];
                c1 += wie * s_wemb[e * IN_DIM + 2 * jj + 1];
            }
            wc[gi][jj] = pack2(c0, c1);
        }
#pragma unroll
        for (int jj = 0; jj < H_DIM / 2; ++jj)
            wh[gi][jj] = pack2(Whh[r * H_DIM + 2 * jj], Whh[r * H_DIM + 2 * jj + 1]);
    }

    // ---- X prefetch prologue: stage x[0], x[1]; hold x[2] in register ----
    const int  xbase = blockIdx.x * (ROWS_PB * IN_DIM);
    const bool isPre = (tid < ROWS_PB * IN_DIM) && (xbase + tid < BATCH * IN_DIM);
    const long long xstride = (long long)BATCH * IN_DIM;
    float xprev = 0.0f;
    if (isPre) {
        (&x_s[0][0][0])[tid] = X[xbase + tid];
        (&x_s[1][0][0])[tid] = X[xstride + xbase + tid];
        xprev               = X[2 * xstride + xbase + tid];
    }
    float c = 0.0f;
    __syncthreads();

    int buf = 0;
    int xb = 0, xw = 2;   // read buffer t%3, write buffer (t+2)%3

    for (int t = 0; t < T_STEPS; ++t) {
        // stage x[t+2] (loaded last iter), launch LDG for x[t+3]
        if (isPre) {
            (&x_s[xw][0][0])[tid] = xprev;
            if (t + 3 < T_STEPS)
                xprev = X[(long long)(t + 3) * xstride + xbase + tid];
        }

        // ---- two gate dot-products (f32x2, operands loaded pre-packed) ----
        unsigned long long a0 = pack2(bc[0], 0.0f);
        unsigned long long a1 = pack2(bc[1], 0.0f);

        // x[0..11]: three 16B loads at float offsets 0, 4, 8
        unsigned long long q0, q1, q2, q3, q4, q5;
        const float* xp = x_s[xb][row];
        lds2(q0, q1, xp);        // x[0..3]
        lds2(q2, q3, xp + 4);    // x[4..7]
        lds2(q4, q5, xp + 8);    // x[8..11]
        fma2(a0, wc[0][0], q0); fma2(a1, wc[1][0], q0);
        fma2(a0, wc[0][1], q1); fma2(a1, wc[1][1], q1);
        fma2(a0, wc[0][2], q2); fma2(a1, wc[1][2], q2);
        fma2(a0, wc[0][3], q3); fma2(a1, wc[1][3], q3);
        fma2(a0, wc[0][4], q4); fma2(a1, wc[1][4], q4);
        fma2(a0, wc[0][5], q5); fma2(a1, wc[1][5], q5);

        unsigned long long hq[10];
        const float* hp = h_s[buf][row];
        lds2(hq[0], hq[1], hp);
        lds2(hq[2], hq[3], hp + 4);
        lds2(hq[4], hq[5], hp + 8);
        lds2(hq[6], hq[7], hp + 12);
        lds2(hq[8], hq[9], hp + 16);
#pragma unroll
        for (int jj = 0; jj < H_DIM / 2; ++jj) {
            fma2(a0, wh[0][jj], hq[jj]);
            fma2(a1, wh[1][jj], hq[jj]);
        }

        const float pre0 = hsum2(a0);
        const float pre1 = hsum2(a1);

        // half0: p = sigmoid(i)*tanh(g);  half1: fv = sigmoid(f), ov = sigmoid(o)
        float sendv, ov = 0.0f;
        if (half == 0) {
            sendv = sig_a(pre0) * tanh_a(pre1);      // p
        } else {
            sendv = sig_a(pre0);                     // fv
            ov    = sig_a(pre1);
        }
        const float other = __shfl_xor_sync(0xffffffffu, sendv, 1);
        const float fv = half ? sendv : other;
        const float p  = half ? other : sendv;
        c = fmaf(fv, c, p);

        if (half) h_s[buf ^ 1][row][k] = ov * tanh_a(c);

        // out-projection for step t-1, reusing hq (= h_{t-1}) registers
        if (half == 0 && k < 3 && t > 0 && valid) {
            unsigned long long oa = pack2(s_bout[k], 0.0f);
            const float* wp = &s_wout[k * H_DIM];
            unsigned long long w0, w1;
#pragma unroll
            for (int q = 0; q < 5; ++q) {
                lds2(w0, w1, wp + 4 * q);
                fma2(oa, w0, hq[2 * q]);
                fma2(oa, w1, hq[2 * q + 1]);
            }
            out[(long long)(t - 1) * (BATCH * 3) + grow * 3 + k] = hsum2(oa);
        }

        __syncthreads();
        buf ^= 1;
        xb = (xb == 2) ? 0 : xb + 1;
        xw = (xw == 2) ? 0 : xw + 1;
    }

    // final output for t = T-1 (h_{T-1} in h_s[buf])
    if (half == 0 && k < 3 && valid) {
        unsigned long long hq2[10];
        const float* hp = h_s[buf][row];
        lds2(hq2[0], hq2[1], hp);
        lds2(hq2[2], hq2[3], hp + 4);
        lds2(hq2[4], hq2[5], hp + 8);
        lds2(hq2[6], hq2[7], hp + 12);
        lds2(hq2[8], hq2[9], hp + 16);
        unsigned long long oa = pack2(s_bout[k], 0.0f);
        const float* wp = &s_wout[k * H_DIM];
        unsigned long long w0, w1;
#pragma unroll
        for (int q = 0; q < 5; ++q) {
            lds2(w0, w1, wp + 4 * q);
            fma2(oa, w0, hq2[2 * q]);
            fma2(oa, w1, hq2[2 * q + 1]);
        }
        out[(long long)(T_STEPS - 1) * (BATCH * 3) + grow * 3 + k] = hsum2(oa);
    }
}

extern "C" void kernel_launch(void* const* d_in, const int* in_sizes, int n_in,
                              void* d_out, int out_size) {
    const float* X    = (const float*)d_in[0];
    const float* Wemb = (const float*)d_in[1];
    const float* bemb = (const float*)d_in[2];
    const float* Wih  = (const float*)d_in[3];
    const float* bih  = (const float*)d_in[4];
    const float* Whh  = (const float*)d_in[5];
    const float* bhh  = (const float*)d_in[6];
    const float* Wout = (const float*)d_in[7];
    const float* bout = (const float*)d_in[8];
    float* out = (float*)d_out;

    lstm_tracker_kernel<<<NGRID, NTHREADS>>>(X, Wemb, bemb, Wih, bih,
                                             Whh, bhh, Wout, bout, out);
}

// round 5
// speedup vs baseline: 1.2967x; 1.2967x over previous
#include <cuda_runtime.h>
#include <cstdint>

#define T_STEPS 512
#define BATCH   2048
#define IN_DIM  12
#define E_DIM   15
#define H_DIM   20
#define ROWS_PB 14
#define NTHREADS (ROWS_PB * H_DIM)                  // 280
#define NGRID   ((BATCH + ROWS_PB - 1) / ROWS_PB)   // 147 -> 1 block/SM
#define CHUNK   8                                   // X prefetch chunk (steps)
#define XPT     (ROWS_PB * IN_DIM)                  // 168 x-elements per step

// ---- packed f32x2 helpers (Blackwell sm_103a) ----
__device__ __forceinline__ unsigned long long pack2(float x, float y) {
    unsigned long long u;
    asm("mov.b64 %0, {%1, %2};" : "=l"(u) : "f"(x), "f"(y));
    return u;
}
__device__ __forceinline__ void fma2(unsigned long long& d,
                                     unsigned long long a,
                                     unsigned long long b) {
    asm("fma.rn.f32x2 %0, %1, %2, %0;" : "+l"(d) : "l"(a), "l"(b));
}
__device__ __forceinline__ float hsum2(unsigned long long u) {
    float x, y;
    asm("mov.b64 {%0, %1}, %2;" : "=f"(x), "=f"(y) : "l"(u));
    return x + y;
}
__device__ __forceinline__ float tanh_a(float x) {
    float y;
    asm("tanh.approx.f32 %0, %1;" : "=f"(y) : "f"(x));
    return y;
}
__device__ __forceinline__ float sig_a(float x) {        // sigmoid, 1 MUFU
    return fmaf(0.5f, tanh_a(0.5f * x), 0.5f);
}
// 16B shared load (4 floats) into two aligned u64 pairs (feeds fma.rn.f32x2)
__device__ __forceinline__ void lds2(unsigned long long& a, unsigned long long& b,
                                     const float* p) {
    uint32_t addr = (uint32_t)__cvta_generic_to_shared(p);
    asm volatile("ld.shared.v2.b64 {%0, %1}, [%2];" : "=l"(a), "=l"(b) : "r"(addr));
}

__global__ void __launch_bounds__(NTHREADS, 1)
lstm_tracker_kernel(const float* __restrict__ X,
                    const float* __restrict__ Wemb, const float* __restrict__ bemb,
                    const float* __restrict__ Wih,  const float* __restrict__ bih,
                    const float* __restrict__ Whh,  const float* __restrict__ bhh,
                    const float* __restrict__ Wout, const float* __restrict__ bout,
                    float* __restrict__ out)
{
    __shared__ __align__(16) float s_wemb[E_DIM * IN_DIM];
    __shared__ __align__(16) float s_wih[4 * H_DIM * E_DIM];
    __shared__ __align__(16) float s_wout[3 * H_DIM];
    __shared__ float s_bout[3];
    __shared__ float s_bemb[E_DIM];
    __shared__ __align__(16) float x_s[2][CHUNK][XPT];       // chunked double buffer
    __shared__ __align__(16) float h_s[2][ROWS_PB][H_DIM];   // ping-pong h

    const int tid  = threadIdx.x;
    const int row  = tid / H_DIM;        // local batch row 0..13
    const int k    = tid % H_DIM;        // hidden unit owned by this thread
    const int grow = blockIdx.x * ROWS_PB + row;
    const bool valid = grow < BATCH;

    // ---- cooperative weight staging ----
    for (int i = tid; i < E_DIM * IN_DIM; i += NTHREADS)     s_wemb[i] = Wemb[i];
    for (int i = tid; i < 4 * H_DIM * E_DIM; i += NTHREADS)  s_wih[i]  = Wih[i];
    if (tid < 3 * H_DIM) s_wout[tid] = Wout[tid];
    if (tid < 3)         s_bout[tid] = bout[tid];
    if (tid < E_DIM)     s_bemb[tid] = bemb[tid];
    h_s[0][row][k] = 0.0f;
    h_s[1][row][k] = 0.0f;
    __syncthreads();

    // ---- per-thread register weights (invariant over t) ----
    // Fused: Wc[r][j] = sum_e Wih[r][e]*Wemb[e][j],  r = g*H + k
    //        bc[g]    = bih[r] + bhh[r] + sum_e Wih[r][e]*bemb[e]
    float bc[4];
    unsigned long long wc[4][IN_DIM / 2];   // 24 u64
    unsigned long long wh[4][H_DIM / 2];    // 40 u64
#pragma unroll
    for (int g = 0; g < 4; ++g) {
        const int r = g * H_DIM + k;
        float b = bih[r] + bhh[r];
#pragma unroll
        for (int e = 0; e < E_DIM; ++e) b += s_wih[r * E_DIM + e] * s_bemb[e];
        bc[g] = b;
#pragma unroll
        for (int jj = 0; jj < IN_DIM / 2; ++jj) {
            float c0 = 0.0f, c1 = 0.0f;
#pragma unroll
            for (int e = 0; e < E_DIM; ++e) {
                const float wie = s_wih[r * E_DIM + e];
                c0 += wie * s_wemb[e * IN_DIM + 2 * jj];
                c1 += wie * s_wemb[e * IN_DIM + 2 * jj + 1];
            }
            wc[g][jj] = pack2(c0, c1);
        }
#pragma unroll
        for (int jj = 0; jj < H_DIM / 2; ++jj)
            wh[g][jj] = pack2(Whh[r * H_DIM + 2 * jj], Whh[r * H_DIM + 2 * jj + 1]);
    }

    // ---- X prefetch prologue ----
    // chunk 0 (steps 0..7): LDG+STS directly. chunk 1 (steps 8..15): into regs.
    const int  xbase = blockIdx.x * XPT;
    const bool isPre = (tid < XPT) && (xbase + tid < BATCH * IN_DIM);
    const long long xstride = (long long)BATCH * IN_DIM;
    float xr[CHUNK];
    if (isPre) {
#pragma unroll
        for (int s = 0; s < CHUNK; ++s)
            x_s[0][s][tid] = X[(long long)s * xstride + xbase + tid];
#pragma unroll
        for (int s = 0; s < CHUNK; ++s)
            xr[s] = X[(long long)(CHUNK + s) * xstride + xbase + tid];
    }
    float c = 0.0f;
    __syncthreads();

    int buf = 0;

    for (int t = 0; t < T_STEPS; ++t) {
        // chunk boundary: stage chunk (t/8 + 1) from regs, LDG chunk (t/8 + 2).
        // Staged buffer is only read starting at step t+8; the buffer being
        // overwritten was last read at step t-1 (barrier-separated). LDG->STS
        // slack is 8 full steps.
        if ((t & (CHUNK - 1)) == 0 && (t + CHUNK) < T_STEPS && isPre) {
            const int nb = ((t >> 3) + 1) & 1;
#pragma unroll
            for (int s = 0; s < CHUNK; ++s) x_s[nb][s][tid] = xr[s];
            const int bt = t + 2 * CHUNK;
#pragma unroll
            for (int s = 0; s < CHUNK; ++s)
                xr[s] = (bt + s < T_STEPS)
                      ? X[(long long)(bt + s) * xstride + xbase + tid] : 0.0f;
        }

        // ---- 4 gate dot-products, operands pre-packed via LDS.128 ----
        unsigned long long a0 = pack2(bc[0], 0.0f);
        unsigned long long a1 = pack2(bc[1], 0.0f);
        unsigned long long a2 = pack2(bc[2], 0.0f);
        unsigned long long a3 = pack2(bc[3], 0.0f);

        const float* xp = &x_s[(t >> 3) & 1][t & (CHUNK - 1)][row * IN_DIM];
        unsigned long long q0, q1, q2, q3, q4, q5;
        lds2(q0, q1, xp);        // x[0..3]
        lds2(q2, q3, xp + 4);    // x[4..7]
        lds2(q4, q5, xp + 8);    // x[8..11]
        fma2(a0, wc[0][0], q0); fma2(a1, wc[1][0], q0); fma2(a2, wc[2][0], q0); fma2(a3, wc[3][0], q0);
        fma2(a0, wc[0][1], q1); fma2(a1, wc[1][1], q1); fma2(a2, wc[2][1], q1); fma2(a3, wc[3][1], q1);
        fma2(a0, wc[0][2], q2); fma2(a1, wc[1][2], q2); fma2(a2, wc[2][2], q2); fma2(a3, wc[3][2], q2);
        fma2(a0, wc[0][3], q3); fma2(a1, wc[1][3], q3); fma2(a2, wc[2][3], q3); fma2(a3, wc[3][3], q3);
        fma2(a0, wc[0][4], q4); fma2(a1, wc[1][4], q4); fma2(a2, wc[2][4], q4); fma2(a3, wc[3][4], q4);
        fma2(a0, wc[0][5], q5); fma2(a1, wc[1][5], q5); fma2(a2, wc[2][5], q5); fma2(a3, wc[3][5], q5);

        unsigned long long hq[10];
        const float* hp = h_s[buf][row];
        lds2(hq[0], hq[1], hp);
        lds2(hq[2], hq[3], hp + 4);
        lds2(hq[4], hq[5], hp + 8);
        lds2(hq[6], hq[7], hp + 12);
        lds2(hq[8], hq[9], hp + 16);
#pragma unroll
        for (int jj = 0; jj < H_DIM / 2; ++jj) {
            fma2(a0, wh[0][jj], hq[jj]);
            fma2(a1, wh[1][jj], hq[jj]);
            fma2(a2, wh[2][jj], hq[jj]);
            fma2(a3, wh[3][jj], hq[jj]);
        }

        const float iv = sig_a(hsum2(a0));
        const float fv = sig_a(hsum2(a1));
        const float gv = tanh_a(hsum2(a2));
        const float ov = sig_a(hsum2(a3));
        c = fmaf(fv, c, iv * gv);
        h_s[buf ^ 1][row][k] = ov * tanh_a(c);

        // out-projection for step t-1 (hq = h_{t-1}, already in registers)
        if (k < 3 && t > 0 && valid) {
            unsigned long long oa = pack2(s_bout[k], 0.0f);
            const float* wp = &s_wout[k * H_DIM];
            unsigned long long w0, w1;
#pragma unroll
            for (int q = 0; q < 5; ++q) {
                lds2(w0, w1, wp + 4 * q);
                fma2(oa, w0, hq[2 * q]);
                fma2(oa, w1, hq[2 * q + 1]);
            }
            out[(long long)(t - 1) * (BATCH * 3) + grow * 3 + k] = hsum2(oa);
        }

        __syncthreads();
        buf ^= 1;
    }

    // final output for t = T-1 (h_{T-1} lives in h_s[buf])
    if (k < 3 && valid) {
        unsigned long long hq2[10];
        const float* hp = h_s[buf][row];
        lds2(hq2[0], hq2[1], hp);
        lds2(hq2[2], hq2[3], hp + 4);
        lds2(hq2[4], hq2[5], hp + 8);
        lds2(hq2[6], hq2[7], hp + 12);
        lds2(hq2[8], hq2[9], hp + 16);
        unsigned long long oa = pack2(s_bout[k], 0.0f);
        const float* wp = &s_wout[k * H_DIM];
        unsigned long long w0, w1;
#pragma unroll
        for (int q = 0; q < 5; ++q) {
            lds2(w0, w1, wp + 4 * q);
            fma2(oa, w0, hq2[2 * q]);
            fma2(oa, w1, hq2[2 * q + 1]);
        }
        out[(long long)(T_STEPS - 1) * (BATCH * 3) + grow * 3 + k] = hsum2(oa);
    }
}

extern "C" void kernel_launch(void* const* d_in, const int* in_sizes, int n_in,
                              void* d_out, int out_size) {
    const float* X    = (const float*)d_in[0];
    const float* Wemb = (const float*)d_in[1];
    const float* bemb = (const float*)d_in[2];
    const float* Wih  = (const float*)d_in[3];
    const float* bih  = (const float*)d_in[4];
    const float* Whh  = (const float*)d_in[5];
    const float* bhh  = (const float*)d_in[6];
    const float* Wout = (const float*)d_in[7];
    const float* bout = (const float*)d_in[8];
    float* out = (float*)d_out;

    lstm_tracker_kernel<<<NGRID, NTHREADS>>>(X, Wemb, bemb, Wih, bih,
                                             Whh, bhh, Wout, bout, out);
}